// round 9
// baseline (speedup 1.0000x reference)
#include <cuda_runtime.h>
#include <cstdint>

// Problem constants
#define N_TOK  262144
#define K_CB   1024
#define D_EMB  64
#define DECAY  0.99f
#define EPSV   1e-5f
#define COMMIT 0.25f

// Output layout (float32 blob, reference return order)
#define OFF_Q    0
#define OFF_LOSS 16777216
#define OFF_IDX  16777217
#define OFF_CB   17039361   // odd -> only 4-byte aligned
#define OFF_CS   17104897
#define OFF_EW   17105921   // odd -> only 4-byte aligned

// Scratch (device globals; no allocations allowed)
__device__ float    g_dw[K_CB * D_EMB];
__device__ float    g_counts[K_CB];
__device__ float    g_loss;
__device__ float    g_cnorm[K_CB];
__device__ float    g_n;
__device__ unsigned g_cbt[K_CB * D_EMB];   // codebook as tf32 bit patterns
__device__ unsigned g_xmax2;               // max ||x||^2 (float bits)
__device__ unsigned g_cmax2;               // max ||c||^2 (float bits)

// ---------------------------------------------------------------------------
__device__ __forceinline__ unsigned f2tf32(float f) {
    unsigned r; asm("cvt.rna.tf32.f32 %0, %1;" : "=r"(r) : "f"(f)); return r;
}

__device__ __forceinline__ void mma_tf32(float c[4], const unsigned a[4],
                                         unsigned b0, unsigned b1) {
    asm volatile(
        "mma.sync.aligned.m16n8k8.row.col.f32.tf32.tf32.f32 "
        "{%0,%1,%2,%3}, {%4,%5,%6,%7}, {%8,%9}, {%0,%1,%2,%3};"
        : "+f"(c[0]), "+f"(c[1]), "+f"(c[2]), "+f"(c[3])
        : "r"(a[0]), "r"(a[1]), "r"(a[2]), "r"(a[3]), "r"(b0), "r"(b1));
}

// Exact distance, bit-identical to the validated R2 chain ordering.
__device__ __forceinline__ float exact_d(const float4* x4, const float* crow, float cn) {
    const float4* c4 = reinterpret_cast<const float4*>(crow);
    float s0 = 0.f, s1 = 0.f, s2 = 0.f, s3 = 0.f;
#pragma unroll
    for (int i = 0; i < 16; i++) {
        float4 c = c4[i];
        s0 = fmaf(x4[i].x, c.x, s0);
        s1 = fmaf(x4[i].y, c.y, s1);
        s2 = fmaf(x4[i].z, c.z, s2);
        s3 = fmaf(x4[i].w, c.w, s3);
    }
    return cn - 2.0f * ((s0 + s1) + (s2 + s3));
}

// branchless (m1,i1,m2) tracker update
__device__ __forceinline__ void trk(float& m1, int& i1, float& m2, float d, int j) {
    bool lt = d < m1;
    m2 = lt ? m1 : fminf(m2, d);
    i1 = lt ? j  : i1;
    m1 = lt ? d  : m1;
}

// ---------------------------------------------------------------------------
__global__ void vq_zero_kernel() {
    int i = blockIdx.x * blockDim.x + threadIdx.x;
    if (i < K_CB * D_EMB) g_dw[i] = 0.0f;
    if (i < K_CB)         g_counts[i] = 0.0f;
    if (i == 0) { g_loss = 0.0f; g_xmax2 = 0u; g_cmax2 = 0u; }
}

// ---------------------------------------------------------------------------
// Prep codebook: exact cnorm (R2 chain), tf32 conversion, max ||c||^2.
// ---------------------------------------------------------------------------
__global__ void __launch_bounds__(K_CB)
vq_prep_cb_kernel(const float* __restrict__ codebook) {
    __shared__ float s_m[32];
    int k = threadIdx.x;
    const float4* c = reinterpret_cast<const float4*>(codebook + (size_t)k * D_EMB);
    float s0 = 0.f, s1 = 0.f, s2 = 0.f, s3 = 0.f;
#pragma unroll
    for (int i = 0; i < 16; i++) {
        float4 v = c[i];
        s0 += v.x * v.x; s1 += v.y * v.y;
        s2 += v.z * v.z; s3 += v.w * v.w;
    }
    float cn = (s0 + s1) + (s2 + s3);
    g_cnorm[k] = cn;
#pragma unroll
    for (int i = 0; i < D_EMB; i++)
        g_cbt[(size_t)k * D_EMB + i] = f2tf32(codebook[(size_t)k * D_EMB + i]);
    float m = cn;
#pragma unroll
    for (int o = 16; o > 0; o >>= 1) m = fmaxf(m, __shfl_xor_sync(~0u, m, o));
    if ((k & 31) == 0) s_m[k >> 5] = m;
    __syncthreads();
    if (k == 0) {
        float t = s_m[0];
        for (int w = 1; w < 32; w++) t = fmaxf(t, s_m[w]);
        atomicMax(&g_cmax2, __float_as_uint(t));
    }
}

// ---------------------------------------------------------------------------
// Prep inputs: max ||x||^2 over all tokens.
// ---------------------------------------------------------------------------
__global__ void __launch_bounds__(256)
vq_prep_x_kernel(const float* __restrict__ inputs) {
    __shared__ float s_m[8];
    int t = blockIdx.x * 256 + threadIdx.x;
    const float4* x = reinterpret_cast<const float4*>(inputs + (size_t)t * D_EMB);
    float s = 0.f;
#pragma unroll
    for (int i = 0; i < 16; i++) {
        float4 v = x[i];
        s += v.x * v.x + v.y * v.y + v.z * v.z + v.w * v.w;
    }
#pragma unroll
    for (int o = 16; o > 0; o >>= 1) s = fmaxf(s, __shfl_xor_sync(~0u, s, o));
    if ((threadIdx.x & 31) == 0) s_m[threadIdx.x >> 5] = s;
    __syncthreads();
    if (threadIdx.x == 0) {
        float m = s_m[0];
        for (int w = 1; w < 8; w++) m = fmaxf(m, s_m[w]);
        atomicMax(&g_xmax2, __float_as_uint(m));
    }
}

// ---------------------------------------------------------------------------
// Screen kernel, SINGLE sweep:
//  - tf32 mma computes d~ for all (token, code)
//  - per-row (m1,i1,m2) trackers, quad-merged after the sweep
//  - m2 > m1 + 2W  -> i1 is provably the unique exact argmin (no rescore)
//  - else          -> token is "ambiguous"; resolved by warp-cooperative
//                     exact scans (R2 chain, reference tie rule)
// Fused epilogue: quantized gather, idx, loss, dw atomics, counts.
// ---------------------------------------------------------------------------
#define SC_TPB   128
#define SC_TOKS  128
#define SC_CHUNK 128
#define CBS      68     // smem row stride (words) -> conflict-free B loads

__global__ void __launch_bounds__(SC_TPB)
vq_screen_kernel(const float* __restrict__ inputs,
                 const float* __restrict__ codebook,
                 float* __restrict__ out) {
    __shared__ unsigned s_cb[SC_CHUNK * CBS];     // tf32 chunk
    __shared__ float    s_cn[SC_CHUNK];
    __shared__ int      s_idx[SC_TOKS];
    __shared__ int      s_alist[SC_TOKS];
    __shared__ int      s_acnt;
    __shared__ float    s_counts[K_CB];
    __shared__ float    s_red[SC_TPB / 32];

    const int tid  = threadIdx.x;
    const int warp = tid >> 5;
    const int lane = tid & 31;
    const int g    = lane >> 2;    // group id (row for A/C, code row for B)
    const int tq   = lane & 3;     // thread-in-group
    const int blkTok = blockIdx.x * SC_TOKS;
    const int tokBase = blkTok + warp * 32;

    if (tid == 0) s_acnt = 0;
    for (int i = tid; i < K_CB; i += SC_TPB) s_counts[i] = 0.0f;

    // rigorous screen error bound (validated in R8)
    const float W = 2.4e-3f * sqrtf(__uint_as_float(g_xmax2))
                            * sqrtf(__uint_as_float(g_cmax2)) + 1e-3f;
    const float WIN = 2.0f * W;

    // A fragments for both token tiles, all 8 k-steps (held in regs)
    unsigned afr[2][8][4];
#pragma unroll
    for (int T = 0; T < 2; T++) {
        const int r0 = tokBase + T * 16 + g;
        const int r1 = r0 + 8;
        const float* x0 = inputs + (size_t)r0 * D_EMB;
        const float* x1 = inputs + (size_t)r1 * D_EMB;
#pragma unroll
        for (int q = 0; q < 8; q++) {
            afr[T][q][0] = f2tf32(x0[q * 8 + tq]);
            afr[T][q][1] = f2tf32(x1[q * 8 + tq]);
            afr[T][q][2] = f2tf32(x0[q * 8 + tq + 4]);
            afr[T][q][3] = f2tf32(x1[q * 8 + tq + 4]);
        }
    }

    // trackers per (token tile T, row half r)
    float m1[2][2] = {{3.4e38f, 3.4e38f}, {3.4e38f, 3.4e38f}};
    float m2[2][2] = {{3.4e38f, 3.4e38f}, {3.4e38f, 3.4e38f}};
    int   i1[2][2] = {{0, 0}, {0, 0}};

    for (int ch = 0; ch < K_CB / SC_CHUNK; ch++) {
        __syncthreads();
        for (int i = tid; i < SC_CHUNK * D_EMB; i += SC_TPB) {
            int code = i >> 6, d = i & 63;
            s_cb[code * CBS + d] = g_cbt[(size_t)(ch * SC_CHUNK + code) * D_EMB + d];
        }
        if (tid < SC_CHUNK) s_cn[tid] = g_cnorm[ch * SC_CHUNK + tid];
        __syncthreads();

        for (int tile = 0; tile < SC_CHUNK / 8; tile++) {
            float c0[4] = {0.f, 0.f, 0.f, 0.f};
            float c1[4] = {0.f, 0.f, 0.f, 0.f};
            const unsigned* bb = s_cb + (tile * 8 + g) * CBS;
#pragma unroll
            for (int q = 0; q < 8; q++) {
                unsigned b0 = bb[q * 8 + tq];
                unsigned b1 = bb[q * 8 + tq + 4];
                mma_tf32(c0, afr[0][q], b0, b1);
                mma_tf32(c1, afr[1][q], b0, b1);
            }
            const int col0 = tile * 8 + tq * 2;
            const int j0 = ch * SC_CHUNK + col0, j1 = j0 + 1;
            const float cn0 = s_cn[col0], cn1 = s_cn[col0 + 1];
            trk(m1[0][0], i1[0][0], m2[0][0], fmaf(-2.0f, c0[0], cn0), j0);
            trk(m1[0][0], i1[0][0], m2[0][0], fmaf(-2.0f, c0[1], cn1), j1);
            trk(m1[0][1], i1[0][1], m2[0][1], fmaf(-2.0f, c0[2], cn0), j0);
            trk(m1[0][1], i1[0][1], m2[0][1], fmaf(-2.0f, c0[3], cn1), j1);
            trk(m1[1][0], i1[1][0], m2[1][0], fmaf(-2.0f, c1[0], cn0), j0);
            trk(m1[1][0], i1[1][0], m2[1][0], fmaf(-2.0f, c1[1], cn1), j1);
            trk(m1[1][1], i1[1][1], m2[1][1], fmaf(-2.0f, c1[2], cn0), j0);
            trk(m1[1][1], i1[1][1], m2[1][1], fmaf(-2.0f, c1[3], cn1), j1);
        }
    }

    // quad butterfly merge (lanes tq=0..3 hold disjoint col subsets of same row)
#pragma unroll
    for (int T = 0; T < 2; T++)
#pragma unroll
        for (int r = 0; r < 2; r++) {
            float a1 = m1[T][r], a2 = m2[T][r];
            int   ai = i1[T][r];
#pragma unroll
            for (int o = 1; o <= 2; o <<= 1) {
                float om1 = __shfl_xor_sync(~0u, a1, o);
                int   oi1 = __shfl_xor_sync(~0u, ai, o);
                float om2 = __shfl_xor_sync(~0u, a2, o);
                if (om1 < a1) { a2 = fminf(a1, om2); a1 = om1; ai = oi1; }
                else          { a2 = fminf(a2, om1); }
            }
            if (tq == 0) {
                const int slot = warp * 32 + T * 16 + r * 8 + g;
                s_idx[slot] = ai;
                if (a2 <= a1 + WIN) {
                    int p = atomicAdd(&s_acnt, 1);
                    s_alist[p] = slot;
                }
            }
        }
    __syncthreads();

    // ---- ambiguous tokens: warp-cooperative exact scans --------------------
    const int acnt = s_acnt;
    for (int a = warp; a < acnt; a += SC_TPB / 32) {
        const int slot = s_alist[a];
        const int gid = blkTok + slot;
        float4 x4[16];
        const float4* xp = reinterpret_cast<const float4*>(inputs + (size_t)gid * D_EMB);
#pragma unroll
        for (int i = 0; i < 16; i++) x4[i] = xp[i];
        float bd = 3.4028235e38f;
        int   bj = K_CB;
        for (int c = 0; c < K_CB / 32; c++) {
            int j = c * 32 + lane;
            float d = exact_d(x4, codebook + (size_t)j * D_EMB, g_cnorm[j]);
            if (d < bd) { bd = d; bj = j; }   // within lane: ascending j, strict <
        }
        // cross-lane merge with reference tie rule (smaller j wins on equal d)
#pragma unroll
        for (int o = 16; o > 0; o >>= 1) {
            float od = __shfl_xor_sync(~0u, bd, o);
            int   oj = __shfl_xor_sync(~0u, bj, o);
            if (od < bd || (od == bd && oj < bj)) { bd = od; bj = oj; }
        }
        if (lane == 0) s_idx[slot] = bj;
    }
    __syncthreads();

    // ---- epilogue: thread tid owns block-token slot tid --------------------
    const int gid = blkTok + tid;
    const int bi = s_idx[tid];
    float4 x4[16];
    const float4* xp = reinterpret_cast<const float4*>(inputs + (size_t)gid * D_EMB);
#pragma unroll
    for (int i = 0; i < 16; i++) x4[i] = xp[i];

    atomicAdd(&s_counts[bi], 1.0f);

    const float4* cch = reinterpret_cast<const float4*>(codebook + (size_t)bi * D_EMB);
    float4* qout = reinterpret_cast<float4*>(out + OFF_Q + (size_t)gid * D_EMB);
    float* dwrow = g_dw + (size_t)bi * D_EMB;
    float lsum = 0.0f;
#pragma unroll
    for (int i = 0; i < 16; i++) {
        float4 c4 = cch[i];
        qout[i] = c4;
        float dx = c4.x - x4[i].x, dy = c4.y - x4[i].y;
        float dz = c4.z - x4[i].z, dwv = c4.w - x4[i].w;
        lsum += dx * dx + dy * dy + dz * dz + dwv * dwv;
        atomicAdd(dwrow + 4 * i + 0, x4[i].x);
        atomicAdd(dwrow + 4 * i + 1, x4[i].y);
        atomicAdd(dwrow + 4 * i + 2, x4[i].z);
        atomicAdd(dwrow + 4 * i + 3, x4[i].w);
    }
    out[OFF_IDX + gid] = (float)bi;

    // block loss reduction
#pragma unroll
    for (int o = 16; o > 0; o >>= 1)
        lsum += __shfl_xor_sync(~0u, lsum, o);
    if (lane == 0) s_red[warp] = lsum;
    __syncthreads();
    if (tid == 0) {
        float t = 0.f;
#pragma unroll
        for (int w = 0; w < SC_TPB / 32; w++) t += s_red[w];
        atomicAdd(&g_loss, t);
    }

    // flush block-local counts
    for (int i = tid; i < K_CB; i += SC_TPB) {
        float v = s_counts[i];
        if (v != 0.0f) atomicAdd(&g_counts[i], v);
    }
}

// ---------------------------------------------------------------------------
// Finalize stage 1: new_cluster_size, n-reduction, loss. One block.
// ---------------------------------------------------------------------------
__global__ void __launch_bounds__(K_CB)
vq_ncs_kernel(const float* __restrict__ ema_cs, float* __restrict__ out) {
    __shared__ float s_n[K_CB];
    const int k = threadIdx.x;

    float ncs = DECAY * ema_cs[k] + (1.0f - DECAY) * g_counts[k];
    out[OFF_CS + k] = ncs;

    s_n[k] = ncs;
    __syncthreads();
#pragma unroll
    for (int s = K_CB / 2; s > 0; s >>= 1) {
        if (k < s) s_n[k] += s_n[k + s];
        __syncthreads();
    }
    if (k == 0) {
        g_n = s_n[0];
        out[OFF_LOSS] = COMMIT * g_loss / (float)((size_t)N_TOK * D_EMB);
    }
}

// ---------------------------------------------------------------------------
// Finalize stage 2: element-parallel EMA weight + codebook update.
// ---------------------------------------------------------------------------
__global__ void __launch_bounds__(256)
vq_update_kernel(const float* __restrict__ ema_w, float* __restrict__ out) {
    const int idx = blockIdx.x * 256 + threadIdx.x;   // 0 .. K*D-1
    const int k = idx >> 6;

    float ncs = out[OFF_CS + k];
    float n = g_n;
    float smoothed = (ncs + EPSV) / (n + (float)K_CB * EPSV) * n;

    float w = DECAY * ema_w[idx] + (1.0f - DECAY) * g_dw[idx];
    out[OFF_EW + idx] = w;
    out[OFF_CB + idx] = w / smoothed;
}

// ---------------------------------------------------------------------------
extern "C" void kernel_launch(void* const* d_in, const int* in_sizes, int n_in,
                              void* d_out, int out_size) {
    const float* inputs   = (const float*)d_in[0];
    const float* codebook = (const float*)d_in[1];
    const float* ema_cs   = (const float*)d_in[2];
    const float* ema_w    = (const float*)d_in[3];
    float* out = (float*)d_out;

    vq_zero_kernel<<<(K_CB * D_EMB + 255) / 256, 256>>>();
    vq_prep_cb_kernel<<<1, K_CB>>>(codebook);
    vq_prep_x_kernel<<<N_TOK / 256, 256>>>(inputs);
    vq_screen_kernel<<<N_TOK / SC_TOKS, SC_TPB>>>(inputs, codebook, out);
    vq_ncs_kernel<<<1, K_CB>>>(ema_cs, out);
    vq_update_kernel<<<(K_CB * D_EMB) / 256, 256>>>(ema_w, out);
}

// round 10
// speedup vs baseline: 2.5326x; 2.5326x over previous
#include <cuda_runtime.h>
#include <cstdint>

// Problem constants
#define N_TOK  262144
#define K_CB   1024
#define D_EMB  64
#define DECAY  0.99f
#define EPSV   1e-5f
#define COMMIT 0.25f

// Output layout (float32 blob, reference return order)
#define OFF_Q    0
#define OFF_LOSS 16777216
#define OFF_IDX  16777217
#define OFF_CB   17039361   // odd -> only 4-byte aligned
#define OFF_CS   17104897
#define OFF_EW   17105921   // odd -> only 4-byte aligned

// Scratch (device globals; no allocations allowed)
__device__ float    g_dw[K_CB * D_EMB];
__device__ float    g_counts[K_CB];
__device__ float    g_loss;
__device__ float    g_cnorm[K_CB];
__device__ float    g_n;
__device__ unsigned g_cbt[K_CB * D_EMB];   // codebook as tf32 bit patterns
__device__ unsigned g_xmax2;               // max ||x||^2 (float bits)
__device__ unsigned g_cmax2;               // max ||c||^2 (float bits)

// ---------------------------------------------------------------------------
__device__ __forceinline__ unsigned f2tf32(float f) {
    unsigned r; asm("cvt.rna.tf32.f32 %0, %1;" : "=r"(r) : "f"(f)); return r;
}

__device__ __forceinline__ void mma_tf32(float c[4], const unsigned a[4],
                                         unsigned b0, unsigned b1) {
    asm volatile(
        "mma.sync.aligned.m16n8k8.row.col.f32.tf32.tf32.f32 "
        "{%0,%1,%2,%3}, {%4,%5,%6,%7}, {%8,%9}, {%0,%1,%2,%3};"
        : "+f"(c[0]), "+f"(c[1]), "+f"(c[2]), "+f"(c[3])
        : "r"(a[0]), "r"(a[1]), "r"(a[2]), "r"(a[3]), "r"(b0), "r"(b1));
}

// Exact distance, bit-identical to the validated R2 chain ordering.
__device__ __forceinline__ float exact_d(const float4* x4, const float* crow, float cn) {
    const float4* c4 = reinterpret_cast<const float4*>(crow);
    float s0 = 0.f, s1 = 0.f, s2 = 0.f, s3 = 0.f;
#pragma unroll
    for (int i = 0; i < 16; i++) {
        float4 c = c4[i];
        s0 = fmaf(x4[i].x, c.x, s0);
        s1 = fmaf(x4[i].y, c.y, s1);
        s2 = fmaf(x4[i].z, c.z, s2);
        s3 = fmaf(x4[i].w, c.w, s3);
    }
    return cn - 2.0f * ((s0 + s1) + (s2 + s3));
}

// ---------------------------------------------------------------------------
__global__ void vq_zero_kernel() {
    int i = blockIdx.x * blockDim.x + threadIdx.x;
    if (i < K_CB * D_EMB) g_dw[i] = 0.0f;
    if (i < K_CB)         g_counts[i] = 0.0f;
    if (i == 0) { g_loss = 0.0f; g_xmax2 = 0u; g_cmax2 = 0u; }
}

// ---------------------------------------------------------------------------
// Prep codebook: exact cnorm (R2 chain), tf32 conversion, max ||c||^2.
// ---------------------------------------------------------------------------
__global__ void __launch_bounds__(K_CB)
vq_prep_cb_kernel(const float* __restrict__ codebook) {
    __shared__ float s_m[32];
    int k = threadIdx.x;
    const float4* c = reinterpret_cast<const float4*>(codebook + (size_t)k * D_EMB);
    float s0 = 0.f, s1 = 0.f, s2 = 0.f, s3 = 0.f;
#pragma unroll
    for (int i = 0; i < 16; i++) {
        float4 v = c[i];
        s0 += v.x * v.x; s1 += v.y * v.y;
        s2 += v.z * v.z; s3 += v.w * v.w;
    }
    float cn = (s0 + s1) + (s2 + s3);
    g_cnorm[k] = cn;
#pragma unroll
    for (int i = 0; i < D_EMB; i++)
        g_cbt[(size_t)k * D_EMB + i] = f2tf32(codebook[(size_t)k * D_EMB + i]);
    float m = cn;
#pragma unroll
    for (int o = 16; o > 0; o >>= 1) m = fmaxf(m, __shfl_xor_sync(~0u, m, o));
    if ((k & 31) == 0) s_m[k >> 5] = m;
    __syncthreads();
    if (k == 0) {
        float t = s_m[0];
        for (int w = 1; w < 32; w++) t = fmaxf(t, s_m[w]);
        atomicMax(&g_cmax2, __float_as_uint(t));
    }
}

// ---------------------------------------------------------------------------
// Prep inputs: max ||x||^2 over all tokens.
// ---------------------------------------------------------------------------
__global__ void __launch_bounds__(256)
vq_prep_x_kernel(const float* __restrict__ inputs) {
    __shared__ float s_m[8];
    int t = blockIdx.x * 256 + threadIdx.x;
    const float4* x = reinterpret_cast<const float4*>(inputs + (size_t)t * D_EMB);
    float s = 0.f;
#pragma unroll
    for (int i = 0; i < 16; i++) {
        float4 v = x[i];
        s += v.x * v.x + v.y * v.y + v.z * v.z + v.w * v.w;
    }
#pragma unroll
    for (int o = 16; o > 0; o >>= 1) s = fmaxf(s, __shfl_xor_sync(~0u, s, o));
    if ((threadIdx.x & 31) == 0) s_m[threadIdx.x >> 5] = s;
    __syncthreads();
    if (threadIdx.x == 0) {
        float m = s_m[0];
        for (int w = 1; w < 8; w++) m = fmaxf(m, s_m[w]);
        atomicMax(&g_xmax2, __float_as_uint(m));
    }
}

// ---------------------------------------------------------------------------
// Screen kernel (R8 two-sweep structure, tile-pair ILP):
//   sweep 0: per-token min of d~ (4 independent HMMA chains per iteration)
//   sweep 1: collect all j with d~ <= min + 2W into per-token lists
// Then per-thread exact rescore of candidates (validated R2 chain + first-min
// tie rule), fused with quantized/idx/loss/dw/counts epilogue.
// d~ values are BIT-IDENTICAL to the passing R8 kernel (same per-chain HMMA
// order); the tile-pair restructure is pure instruction scheduling.
// ---------------------------------------------------------------------------
#define SC_TPB   128
#define SC_TOKS  128
#define SC_CHUNK 128
#define CBS      68     // smem row stride (words) -> conflict-free B loads
#define MAXCAND  8

__global__ void __launch_bounds__(SC_TPB)
vq_screen_kernel(const float* __restrict__ inputs,
                 const float* __restrict__ codebook,
                 float* __restrict__ out) {
    __shared__ unsigned s_cb[SC_CHUNK * CBS];     // tf32 chunk
    __shared__ float    s_cn[SC_CHUNK];
    __shared__ int      s_cnt[SC_TOKS];
    __shared__ int      s_list[SC_TOKS * MAXCAND];
    __shared__ float    s_counts[K_CB];
    __shared__ float    s_red[SC_TPB / 32];

    const int tid  = threadIdx.x;
    const int warp = tid >> 5;
    const int lane = tid & 31;
    const int g    = lane >> 2;    // group id (row for A/C, code row for B)
    const int tq   = lane & 3;     // thread-in-group
    const int blkTok = blockIdx.x * SC_TOKS;
    const int tokBase = blkTok + warp * 32;

    if (tid < SC_TOKS) s_cnt[tid] = 0;
    for (int i = tid; i < K_CB; i += SC_TPB) s_counts[i] = 0.0f;

    // rigorous screen error bound (validated in R8)
    const float W = 2.4e-3f * sqrtf(__uint_as_float(g_xmax2))
                            * sqrtf(__uint_as_float(g_cmax2)) + 1e-3f;
    const float WIN = 2.0f * W;

    // A fragments for both token tiles, all 8 k-steps (held in regs)
    unsigned afr[2][8][4];
#pragma unroll
    for (int T = 0; T < 2; T++) {
        const int r0 = tokBase + T * 16 + g;
        const int r1 = r0 + 8;
        const float* x0 = inputs + (size_t)r0 * D_EMB;
        const float* x1 = inputs + (size_t)r1 * D_EMB;
#pragma unroll
        for (int q = 0; q < 8; q++) {
            afr[T][q][0] = f2tf32(x0[q * 8 + tq]);
            afr[T][q][1] = f2tf32(x1[q * 8 + tq]);
            afr[T][q][2] = f2tf32(x0[q * 8 + tq + 4]);
            afr[T][q][3] = f2tf32(x1[q * 8 + tq + 4]);
        }
    }

    float rmin[2][2] = {{3.4e38f, 3.4e38f}, {3.4e38f, 3.4e38f}};
    float thr[2][2]  = {{0.f, 0.f}, {0.f, 0.f}};

    for (int sweep = 0; sweep < 2; sweep++) {
        for (int ch = 0; ch < K_CB / SC_CHUNK; ch++) {
            __syncthreads();
            for (int i = tid; i < SC_CHUNK * D_EMB; i += SC_TPB) {
                int code = i >> 6, d = i & 63;
                s_cb[code * CBS + d] = g_cbt[(size_t)(ch * SC_CHUNK + code) * D_EMB + d];
            }
            if (tid < SC_CHUNK) s_cn[tid] = g_cnorm[ch * SC_CHUNK + tid];
            __syncthreads();

            // tile-pairs: 4 independent HMMA chains per iteration
            for (int tp = 0; tp < SC_CHUNK / 16; tp++) {
                float c00[4] = {0.f, 0.f, 0.f, 0.f};  // tileA x token-tile0
                float c01[4] = {0.f, 0.f, 0.f, 0.f};  // tileA x token-tile1
                float c10[4] = {0.f, 0.f, 0.f, 0.f};  // tileB x token-tile0
                float c11[4] = {0.f, 0.f, 0.f, 0.f};  // tileB x token-tile1
                const unsigned* bbA = s_cb + (tp * 16 + g) * CBS;
                const unsigned* bbB = s_cb + (tp * 16 + 8 + g) * CBS;
#pragma unroll
                for (int q = 0; q < 8; q++) {
                    unsigned a0 = bbA[q * 8 + tq];
                    unsigned a1 = bbA[q * 8 + tq + 4];
                    unsigned b0 = bbB[q * 8 + tq];
                    unsigned b1 = bbB[q * 8 + tq + 4];
                    mma_tf32(c00, afr[0][q], a0, a1);
                    mma_tf32(c01, afr[1][q], a0, a1);
                    mma_tf32(c10, afr[0][q], b0, b1);
                    mma_tf32(c11, afr[1][q], b0, b1);
                }
                const int colA = tp * 16 + tq * 2;
                const int colB = colA + 8;
                const int jA0 = ch * SC_CHUNK + colA, jA1 = jA0 + 1;
                const int jB0 = ch * SC_CHUNK + colB, jB1 = jB0 + 1;
                const float cnA0 = s_cn[colA], cnA1 = s_cn[colA + 1];
                const float cnB0 = s_cn[colB], cnB1 = s_cn[colB + 1];
                float dA00 = fmaf(-2.0f, c00[0], cnA0), dA01 = fmaf(-2.0f, c00[1], cnA1);
                float dA02 = fmaf(-2.0f, c00[2], cnA0), dA03 = fmaf(-2.0f, c00[3], cnA1);
                float dA10 = fmaf(-2.0f, c01[0], cnA0), dA11 = fmaf(-2.0f, c01[1], cnA1);
                float dA12 = fmaf(-2.0f, c01[2], cnA0), dA13 = fmaf(-2.0f, c01[3], cnA1);
                float dB00 = fmaf(-2.0f, c10[0], cnB0), dB01 = fmaf(-2.0f, c10[1], cnB1);
                float dB02 = fmaf(-2.0f, c10[2], cnB0), dB03 = fmaf(-2.0f, c10[3], cnB1);
                float dB10 = fmaf(-2.0f, c11[0], cnB0), dB11 = fmaf(-2.0f, c11[1], cnB1);
                float dB12 = fmaf(-2.0f, c11[2], cnB0), dB13 = fmaf(-2.0f, c11[3], cnB1);
                if (sweep == 0) {
                    rmin[0][0] = fminf(rmin[0][0], fminf(fminf(dA00, dA01), fminf(dB00, dB01)));
                    rmin[0][1] = fminf(rmin[0][1], fminf(fminf(dA02, dA03), fminf(dB02, dB03)));
                    rmin[1][0] = fminf(rmin[1][0], fminf(fminf(dA10, dA11), fminf(dB10, dB11)));
                    rmin[1][1] = fminf(rmin[1][1], fminf(fminf(dA12, dA13), fminf(dB12, dB13)));
                } else {
                    const int s00 = warp * 32 + g;         // tile0 row g
                    const int s01 = s00 + 8;               // tile0 row g+8
                    const int s10 = s00 + 16;              // tile1 row g
                    const int s11 = s00 + 24;              // tile1 row g+8
                    if (dA00 <= thr[0][0]) { int p = atomicAdd(&s_cnt[s00], 1); if (p < MAXCAND) s_list[s00 * MAXCAND + p] = jA0; }
                    if (dA01 <= thr[0][0]) { int p = atomicAdd(&s_cnt[s00], 1); if (p < MAXCAND) s_list[s00 * MAXCAND + p] = jA1; }
                    if (dB00 <= thr[0][0]) { int p = atomicAdd(&s_cnt[s00], 1); if (p < MAXCAND) s_list[s00 * MAXCAND + p] = jB0; }
                    if (dB01 <= thr[0][0]) { int p = atomicAdd(&s_cnt[s00], 1); if (p < MAXCAND) s_list[s00 * MAXCAND + p] = jB1; }
                    if (dA02 <= thr[0][1]) { int p = atomicAdd(&s_cnt[s01], 1); if (p < MAXCAND) s_list[s01 * MAXCAND + p] = jA0; }
                    if (dA03 <= thr[0][1]) { int p = atomicAdd(&s_cnt[s01], 1); if (p < MAXCAND) s_list[s01 * MAXCAND + p] = jA1; }
                    if (dB02 <= thr[0][1]) { int p = atomicAdd(&s_cnt[s01], 1); if (p < MAXCAND) s_list[s01 * MAXCAND + p] = jB0; }
                    if (dB03 <= thr[0][1]) { int p = atomicAdd(&s_cnt[s01], 1); if (p < MAXCAND) s_list[s01 * MAXCAND + p] = jB1; }
                    if (dA10 <= thr[1][0]) { int p = atomicAdd(&s_cnt[s10], 1); if (p < MAXCAND) s_list[s10 * MAXCAND + p] = jA0; }
                    if (dA11 <= thr[1][0]) { int p = atomicAdd(&s_cnt[s10], 1); if (p < MAXCAND) s_list[s10 * MAXCAND + p] = jA1; }
                    if (dB10 <= thr[1][0]) { int p = atomicAdd(&s_cnt[s10], 1); if (p < MAXCAND) s_list[s10 * MAXCAND + p] = jB0; }
                    if (dB11 <= thr[1][0]) { int p = atomicAdd(&s_cnt[s10], 1); if (p < MAXCAND) s_list[s10 * MAXCAND + p] = jB1; }
                    if (dA12 <= thr[1][1]) { int p = atomicAdd(&s_cnt[s11], 1); if (p < MAXCAND) s_list[s11 * MAXCAND + p] = jA0; }
                    if (dA13 <= thr[1][1]) { int p = atomicAdd(&s_cnt[s11], 1); if (p < MAXCAND) s_list[s11 * MAXCAND + p] = jA1; }
                    if (dB12 <= thr[1][1]) { int p = atomicAdd(&s_cnt[s11], 1); if (p < MAXCAND) s_list[s11 * MAXCAND + p] = jB0; }
                    if (dB13 <= thr[1][1]) { int p = atomicAdd(&s_cnt[s11], 1); if (p < MAXCAND) s_list[s11 * MAXCAND + p] = jB1; }
                }
            }
        }
        if (sweep == 0) {
            // quad-reduce lane mins (cols) -> per-row global min -> thresholds
#pragma unroll
            for (int T = 0; T < 2; T++)
#pragma unroll
                for (int r = 0; r < 2; r++) {
                    float v = rmin[T][r];
                    v = fminf(v, __shfl_xor_sync(~0u, v, 1));
                    v = fminf(v, __shfl_xor_sync(~0u, v, 2));
                    thr[T][r] = v + WIN;
                }
        }
    }
    __syncthreads();

    // ---- exact rescore + epilogue: thread tid owns block-token slot tid ----
    const int gid = blkTok + tid;
    float4 x4[16];
    const float4* xp = reinterpret_cast<const float4*>(inputs + (size_t)gid * D_EMB);
#pragma unroll
    for (int i = 0; i < 16; i++) x4[i] = xp[i];

    float best = 3.4028235e38f;
    int   bi = 0;
    const int cnt = s_cnt[tid];
    if (cnt <= MAXCAND) {
        for (int c = 0; c < cnt; c++) {
            int j = s_list[tid * MAXCAND + c];
            float d = exact_d(x4, codebook + (size_t)j * D_EMB, g_cnorm[j]);
            if (d < best || (d == best && j < bi)) { best = d; bi = j; }
        }
    } else {
        // overflow fallback: exact full scan, ascending j, strict <
        for (int j = 0; j < K_CB; j++) {
            float d = exact_d(x4, codebook + (size_t)j * D_EMB, g_cnorm[j]);
            if (d < best) { best = d; bi = j; }
        }
    }

    atomicAdd(&s_counts[bi], 1.0f);

    const float4* cch = reinterpret_cast<const float4*>(codebook + (size_t)bi * D_EMB);
    float4* qout = reinterpret_cast<float4*>(out + OFF_Q + (size_t)gid * D_EMB);
    float* dwrow = g_dw + (size_t)bi * D_EMB;
    float lsum = 0.0f;
#pragma unroll
    for (int i = 0; i < 16; i++) {
        float4 c4 = cch[i];
        qout[i] = c4;
        float dx = c4.x - x4[i].x, dy = c4.y - x4[i].y;
        float dz = c4.z - x4[i].z, dwv = c4.w - x4[i].w;
        lsum += dx * dx + dy * dy + dz * dz + dwv * dwv;
        atomicAdd(dwrow + 4 * i + 0, x4[i].x);
        atomicAdd(dwrow + 4 * i + 1, x4[i].y);
        atomicAdd(dwrow + 4 * i + 2, x4[i].z);
        atomicAdd(dwrow + 4 * i + 3, x4[i].w);
    }
    out[OFF_IDX + gid] = (float)bi;

    // block loss reduction
#pragma unroll
    for (int o = 16; o > 0; o >>= 1)
        lsum += __shfl_xor_sync(~0u, lsum, o);
    if (lane == 0) s_red[warp] = lsum;
    __syncthreads();
    if (tid == 0) {
        float t = 0.f;
#pragma unroll
        for (int w = 0; w < SC_TPB / 32; w++) t += s_red[w];
        atomicAdd(&g_loss, t);
    }

    // flush block-local counts
    for (int i = tid; i < K_CB; i += SC_TPB) {
        float v = s_counts[i];
        if (v != 0.0f) atomicAdd(&g_counts[i], v);
    }
}

// ---------------------------------------------------------------------------
// Finalize stage 1: new_cluster_size, n-reduction, loss. One block.
// ---------------------------------------------------------------------------
__global__ void __launch_bounds__(K_CB)
vq_ncs_kernel(const float* __restrict__ ema_cs, float* __restrict__ out) {
    __shared__ float s_n[K_CB];
    const int k = threadIdx.x;

    float ncs = DECAY * ema_cs[k] + (1.0f - DECAY) * g_counts[k];
    out[OFF_CS + k] = ncs;

    s_n[k] = ncs;
    __syncthreads();
#pragma unroll
    for (int s = K_CB / 2; s > 0; s >>= 1) {
        if (k < s) s_n[k] += s_n[k + s];
        __syncthreads();
    }
    if (k == 0) {
        g_n = s_n[0];
        out[OFF_LOSS] = COMMIT * g_loss / (float)((size_t)N_TOK * D_EMB);
    }
}

// ---------------------------------------------------------------------------
// Finalize stage 2: element-parallel EMA weight + codebook update.
// ---------------------------------------------------------------------------
__global__ void __launch_bounds__(256)
vq_update_kernel(const float* __restrict__ ema_w, float* __restrict__ out) {
    const int idx = blockIdx.x * 256 + threadIdx.x;   // 0 .. K*D-1
    const int k = idx >> 6;

    float ncs = out[OFF_CS + k];
    float n = g_n;
    float smoothed = (ncs + EPSV) / (n + (float)K_CB * EPSV) * n;

    float w = DECAY * ema_w[idx] + (1.0f - DECAY) * g_dw[idx];
    out[OFF_EW + idx] = w;
    out[OFF_CB + idx] = w / smoothed;
}

// ---------------------------------------------------------------------------
extern "C" void kernel_launch(void* const* d_in, const int* in_sizes, int n_in,
                              void* d_out, int out_size) {
    const float* inputs   = (const float*)d_in[0];
    const float* codebook = (const float*)d_in[1];
    const float* ema_cs   = (const float*)d_in[2];
    const float* ema_w    = (const float*)d_in[3];
    float* out = (float*)d_out;

    vq_zero_kernel<<<(K_CB * D_EMB + 255) / 256, 256>>>();
    vq_prep_cb_kernel<<<1, K_CB>>>(codebook);
    vq_prep_x_kernel<<<N_TOK / 256, 256>>>(inputs);
    vq_screen_kernel<<<N_TOK / SC_TOKS, SC_TPB>>>(inputs, codebook, out);
    vq_ncs_kernel<<<1, K_CB>>>(ema_cs, out);
    vq_update_kernel<<<(K_CB * D_EMB) / 256, 256>>>(ema_w, out);
}

// round 11
// speedup vs baseline: 3.1514x; 1.2444x over previous
#include <cuda_runtime.h>
#include <cstdint>

// Problem constants
#define N_TOK  262144
#define K_CB   1024
#define D_EMB  64
#define DECAY  0.99f
#define EPSV   1e-5f
#define COMMIT 0.25f

// Output layout (float32 blob, reference return order)
#define OFF_Q    0
#define OFF_LOSS 16777216
#define OFF_IDX  16777217
#define OFF_CB   17039361   // odd -> only 4-byte aligned
#define OFF_CS   17104897
#define OFF_EW   17105921   // odd -> only 4-byte aligned

// Scratch (device globals; no allocations allowed)
__device__ float    g_dw[K_CB * D_EMB];
__device__ float    g_counts[K_CB];
__device__ float    g_loss;
__device__ float    g_cnorm[K_CB];
__device__ float    g_n;
__device__ unsigned g_cbt[K_CB * D_EMB];   // codebook as tf32 bit patterns
__device__ unsigned g_xmax2;               // max ||x||^2 (float bits)
__device__ unsigned g_cmax2;               // max ||c||^2 (float bits)

// ---------------------------------------------------------------------------
__device__ __forceinline__ unsigned f2tf32(float f) {
    unsigned r; asm("cvt.rna.tf32.f32 %0, %1;" : "=r"(r) : "f"(f)); return r;
}

__device__ __forceinline__ void mma_tf32(float c[4], const unsigned a[4],
                                         unsigned b0, unsigned b1) {
    asm volatile(
        "mma.sync.aligned.m16n8k8.row.col.f32.tf32.tf32.f32 "
        "{%0,%1,%2,%3}, {%4,%5,%6,%7}, {%8,%9}, {%0,%1,%2,%3};"
        : "+f"(c[0]), "+f"(c[1]), "+f"(c[2]), "+f"(c[3])
        : "r"(a[0]), "r"(a[1]), "r"(a[2]), "r"(a[3]), "r"(b0), "r"(b1));
}

// Exact distance, bit-identical to the validated R2 chain ordering.
__device__ __forceinline__ float exact_d(const float4* x4, const float* crow, float cn) {
    const float4* c4 = reinterpret_cast<const float4*>(crow);
    float s0 = 0.f, s1 = 0.f, s2 = 0.f, s3 = 0.f;
#pragma unroll
    for (int i = 0; i < 16; i++) {
        float4 c = c4[i];
        s0 = fmaf(x4[i].x, c.x, s0);
        s1 = fmaf(x4[i].y, c.y, s1);
        s2 = fmaf(x4[i].z, c.z, s2);
        s3 = fmaf(x4[i].w, c.w, s3);
    }
    return cn - 2.0f * ((s0 + s1) + (s2 + s3));
}

// ---------------------------------------------------------------------------
__global__ void vq_zero_kernel() {
    int i = blockIdx.x * blockDim.x + threadIdx.x;
    if (i < K_CB * D_EMB) g_dw[i] = 0.0f;
    if (i < K_CB)         g_counts[i] = 0.0f;
    if (i == 0) { g_loss = 0.0f; g_xmax2 = 0u; g_cmax2 = 0u; }
}

// ---------------------------------------------------------------------------
// Prep codebook: exact cnorm (R2 chain), tf32 conversion, max ||c||^2.
// ---------------------------------------------------------------------------
__global__ void __launch_bounds__(K_CB)
vq_prep_cb_kernel(const float* __restrict__ codebook) {
    __shared__ float s_m[32];
    int k = threadIdx.x;
    const float4* c = reinterpret_cast<const float4*>(codebook + (size_t)k * D_EMB);
    float s0 = 0.f, s1 = 0.f, s2 = 0.f, s3 = 0.f;
#pragma unroll
    for (int i = 0; i < 16; i++) {
        float4 v = c[i];
        s0 += v.x * v.x; s1 += v.y * v.y;
        s2 += v.z * v.z; s3 += v.w * v.w;
    }
    float cn = (s0 + s1) + (s2 + s3);
    g_cnorm[k] = cn;
#pragma unroll
    for (int i = 0; i < D_EMB; i++)
        g_cbt[(size_t)k * D_EMB + i] = f2tf32(codebook[(size_t)k * D_EMB + i]);
    float m = cn;
#pragma unroll
    for (int o = 16; o > 0; o >>= 1) m = fmaxf(m, __shfl_xor_sync(~0u, m, o));
    if ((k & 31) == 0) s_m[k >> 5] = m;
    __syncthreads();
    if (k == 0) {
        float t = s_m[0];
        for (int w = 1; w < 32; w++) t = fmaxf(t, s_m[w]);
        atomicMax(&g_cmax2, __float_as_uint(t));
    }
}

// ---------------------------------------------------------------------------
// Prep inputs: max ||x||^2 over all tokens.
// ---------------------------------------------------------------------------
__global__ void __launch_bounds__(256)
vq_prep_x_kernel(const float* __restrict__ inputs) {
    __shared__ float s_m[8];
    int t = blockIdx.x * 256 + threadIdx.x;
    const float4* x = reinterpret_cast<const float4*>(inputs + (size_t)t * D_EMB);
    float s = 0.f;
#pragma unroll
    for (int i = 0; i < 16; i++) {
        float4 v = x[i];
        s += v.x * v.x + v.y * v.y + v.z * v.z + v.w * v.w;
    }
#pragma unroll
    for (int o = 16; o > 0; o >>= 1) s = fmaxf(s, __shfl_xor_sync(~0u, s, o));
    if ((threadIdx.x & 31) == 0) s_m[threadIdx.x >> 5] = s;
    __syncthreads();
    if (threadIdx.x == 0) {
        float m = s_m[0];
        for (int w = 1; w < 8; w++) m = fmaxf(m, s_m[w]);
        atomicMax(&g_xmax2, __float_as_uint(m));
    }
}

// ---------------------------------------------------------------------------
// Screen kernel — R8 two-sweep structure with FRAGMENT-MAJOR B staging:
// smem layout stores each lane's 16 B-words (k = tq+4m, m=0..15) contiguously
// in a 20-word-padded segment -> B-frag per tile = 4x LDS.128 (was 16x LDS.32),
// 16B-aligned, bank-conflict-free. HMMA ops/operands/chain order are identical
// to the passing R8 kernel -> d~ is bit-identical; pure load-path change.
//   sweep 0: per-token min of d~
//   sweep 1: collect all j with d~ <= min + 2W into per-token lists
// Then per-thread exact rescore (validated R2 chain + first-min tie rule),
// fused with quantized/idx/loss/dw/counts epilogue.
// ---------------------------------------------------------------------------
#define SC_TPB   128
#define SC_TOKS  128
#define SC_CHUNK 128
#define SEGW     20     // 16 payload words + 4 pad: 80B stride, 16B-aligned
#define MAXCAND  8

__global__ void __launch_bounds__(SC_TPB)
vq_screen_kernel(const float* __restrict__ inputs,
                 const float* __restrict__ codebook,
                 float* __restrict__ out) {
    __shared__ unsigned s_cb[(SC_CHUNK / 8) * 32 * SEGW];  // 512 segs * 20 w = 40KB
    __shared__ float    s_cn[SC_CHUNK];
    __shared__ int      s_cnt[SC_TOKS];
    __shared__ int      s_list[SC_TOKS * MAXCAND];
    __shared__ float    s_counts[K_CB];
    __shared__ float    s_red[SC_TPB / 32];

    const int tid  = threadIdx.x;
    const int warp = tid >> 5;
    const int lane = tid & 31;
    const int g    = lane >> 2;    // group id (row for A/C, code row for B)
    const int tq   = lane & 3;     // thread-in-group
    const int blkTok = blockIdx.x * SC_TOKS;
    const int tokBase = blkTok + warp * 32;

    if (tid < SC_TOKS) s_cnt[tid] = 0;
    for (int i = tid; i < K_CB; i += SC_TPB) s_counts[i] = 0.0f;

    // rigorous screen error bound (validated in R8)
    const float W = 2.4e-3f * sqrtf(__uint_as_float(g_xmax2))
                            * sqrtf(__uint_as_float(g_cmax2)) + 1e-3f;
    const float WIN = 2.0f * W;

    // A fragments for both token tiles, all 8 k-steps (held in regs)
    unsigned afr[2][8][4];
#pragma unroll
    for (int T = 0; T < 2; T++) {
        const int r0 = tokBase + T * 16 + g;
        const int r1 = r0 + 8;
        const float* x0 = inputs + (size_t)r0 * D_EMB;
        const float* x1 = inputs + (size_t)r1 * D_EMB;
#pragma unroll
        for (int q = 0; q < 8; q++) {
            afr[T][q][0] = f2tf32(x0[q * 8 + tq]);
            afr[T][q][1] = f2tf32(x1[q * 8 + tq]);
            afr[T][q][2] = f2tf32(x0[q * 8 + tq + 4]);
            afr[T][q][3] = f2tf32(x1[q * 8 + tq + 4]);
        }
    }

    float rmin[2][2] = {{3.4e38f, 3.4e38f}, {3.4e38f, 3.4e38f}};
    float thr[2][2]  = {{0.f, 0.f}, {0.f, 0.f}};

    for (int sweep = 0; sweep < 2; sweep++) {
        for (int ch = 0; ch < K_CB / SC_CHUNK; ch++) {
            __syncthreads();
            // fragment-major staging: seg = (tile*8+g)*4+tq holds words m=k/4
            for (int i = tid; i < SC_CHUNK * D_EMB; i += SC_TPB) {
                int code = i >> 6, d = i & 63;
                int seg = ((code >> 3) << 5) + ((code & 7) << 2) + (d & 3);
                s_cb[seg * SEGW + (d >> 2)] =
                    g_cbt[(size_t)(ch * SC_CHUNK + code) * D_EMB + d];
            }
            if (tid < SC_CHUNK) s_cn[tid] = g_cnorm[ch * SC_CHUNK + tid];
            __syncthreads();

#pragma unroll 4
            for (int tile = 0; tile < SC_CHUNK / 8; tile++) {
                float c0[4] = {0.f, 0.f, 0.f, 0.f};
                float c1[4] = {0.f, 0.f, 0.f, 0.f};
                const unsigned* seg = s_cb + (((tile << 3) + g) * 4 + tq) * SEGW;
                uint4 w0 = *reinterpret_cast<const uint4*>(seg);
                uint4 w1 = *reinterpret_cast<const uint4*>(seg + 4);
                uint4 w2 = *reinterpret_cast<const uint4*>(seg + 8);
                uint4 w3 = *reinterpret_cast<const uint4*>(seg + 12);
                // q-order and operands identical to R8: b0=word[2q], b1=word[2q+1]
                mma_tf32(c0, afr[0][0], w0.x, w0.y);  mma_tf32(c1, afr[1][0], w0.x, w0.y);
                mma_tf32(c0, afr[0][1], w0.z, w0.w);  mma_tf32(c1, afr[1][1], w0.z, w0.w);
                mma_tf32(c0, afr[0][2], w1.x, w1.y);  mma_tf32(c1, afr[1][2], w1.x, w1.y);
                mma_tf32(c0, afr[0][3], w1.z, w1.w);  mma_tf32(c1, afr[1][3], w1.z, w1.w);
                mma_tf32(c0, afr[0][4], w2.x, w2.y);  mma_tf32(c1, afr[1][4], w2.x, w2.y);
                mma_tf32(c0, afr[0][5], w2.z, w2.w);  mma_tf32(c1, afr[1][5], w2.z, w2.w);
                mma_tf32(c0, afr[0][6], w3.x, w3.y);  mma_tf32(c1, afr[1][6], w3.x, w3.y);
                mma_tf32(c0, afr[0][7], w3.z, w3.w);  mma_tf32(c1, afr[1][7], w3.z, w3.w);

                const int col0 = (tile << 3) + tq * 2;
                const int j0 = ch * SC_CHUNK + col0, j1 = j0 + 1;
                const float cn0 = s_cn[col0], cn1 = s_cn[col0 + 1];
                float dA0 = fmaf(-2.0f, c0[0], cn0), dA1 = fmaf(-2.0f, c0[1], cn1);
                float dA2 = fmaf(-2.0f, c0[2], cn0), dA3 = fmaf(-2.0f, c0[3], cn1);
                float dB0 = fmaf(-2.0f, c1[0], cn0), dB1 = fmaf(-2.0f, c1[1], cn1);
                float dB2 = fmaf(-2.0f, c1[2], cn0), dB3 = fmaf(-2.0f, c1[3], cn1);
                if (sweep == 0) {
                    rmin[0][0] = fminf(rmin[0][0], fminf(dA0, dA1));
                    rmin[0][1] = fminf(rmin[0][1], fminf(dA2, dA3));
                    rmin[1][0] = fminf(rmin[1][0], fminf(dB0, dB1));
                    rmin[1][1] = fminf(rmin[1][1], fminf(dB2, dB3));
                } else {
                    const int s00 = warp * 32 + g;         // tile0 row g
                    const int s01 = s00 + 8;               // tile0 row g+8
                    const int s10 = s00 + 16;              // tile1 row g
                    const int s11 = s00 + 24;              // tile1 row g+8
                    if (dA0 <= thr[0][0]) { int p = atomicAdd(&s_cnt[s00], 1); if (p < MAXCAND) s_list[s00 * MAXCAND + p] = j0; }
                    if (dA1 <= thr[0][0]) { int p = atomicAdd(&s_cnt[s00], 1); if (p < MAXCAND) s_list[s00 * MAXCAND + p] = j1; }
                    if (dA2 <= thr[0][1]) { int p = atomicAdd(&s_cnt[s01], 1); if (p < MAXCAND) s_list[s01 * MAXCAND + p] = j0; }
                    if (dA3 <= thr[0][1]) { int p = atomicAdd(&s_cnt[s01], 1); if (p < MAXCAND) s_list[s01 * MAXCAND + p] = j1; }
                    if (dB0 <= thr[1][0]) { int p = atomicAdd(&s_cnt[s10], 1); if (p < MAXCAND) s_list[s10 * MAXCAND + p] = j0; }
                    if (dB1 <= thr[1][0]) { int p = atomicAdd(&s_cnt[s10], 1); if (p < MAXCAND) s_list[s10 * MAXCAND + p] = j1; }
                    if (dB2 <= thr[1][1]) { int p = atomicAdd(&s_cnt[s11], 1); if (p < MAXCAND) s_list[s11 * MAXCAND + p] = j0; }
                    if (dB3 <= thr[1][1]) { int p = atomicAdd(&s_cnt[s11], 1); if (p < MAXCAND) s_list[s11 * MAXCAND + p] = j1; }
                }
            }
        }
        if (sweep == 0) {
            // quad-reduce lane mins (cols) -> per-row global min -> thresholds
#pragma unroll
            for (int T = 0; T < 2; T++)
#pragma unroll
                for (int r = 0; r < 2; r++) {
                    float v = rmin[T][r];
                    v = fminf(v, __shfl_xor_sync(~0u, v, 1));
                    v = fminf(v, __shfl_xor_sync(~0u, v, 2));
                    thr[T][r] = v + WIN;
                }
        }
    }
    __syncthreads();

    // ---- exact rescore + epilogue: thread tid owns block-token slot tid ----
    const int gid = blkTok + tid;
    float4 x4[16];
    const float4* xp = reinterpret_cast<const float4*>(inputs + (size_t)gid * D_EMB);
#pragma unroll
    for (int i = 0; i < 16; i++) x4[i] = xp[i];

    float best = 3.4028235e38f;
    int   bi = 0;
    const int cnt = s_cnt[tid];
    if (cnt <= MAXCAND) {
        for (int c = 0; c < cnt; c++) {
            int j = s_list[tid * MAXCAND + c];
            float d = exact_d(x4, codebook + (size_t)j * D_EMB, g_cnorm[j]);
            if (d < best || (d == best && j < bi)) { best = d; bi = j; }
        }
    } else {
        // overflow fallback: exact full scan, ascending j, strict <
        for (int j = 0; j < K_CB; j++) {
            float d = exact_d(x4, codebook + (size_t)j * D_EMB, g_cnorm[j]);
            if (d < best) { best = d; bi = j; }
        }
    }

    atomicAdd(&s_counts[bi], 1.0f);

    const float4* cch = reinterpret_cast<const float4*>(codebook + (size_t)bi * D_EMB);
    float4* qout = reinterpret_cast<float4*>(out + OFF_Q + (size_t)gid * D_EMB);
    float* dwrow = g_dw + (size_t)bi * D_EMB;
    float lsum = 0.0f;
#pragma unroll
    for (int i = 0; i < 16; i++) {
        float4 c4 = cch[i];
        qout[i] = c4;
        float dx = c4.x - x4[i].x, dy = c4.y - x4[i].y;
        float dz = c4.z - x4[i].z, dwv = c4.w - x4[i].w;
        lsum += dx * dx + dy * dy + dz * dz + dwv * dwv;
        atomicAdd(dwrow + 4 * i + 0, x4[i].x);
        atomicAdd(dwrow + 4 * i + 1, x4[i].y);
        atomicAdd(dwrow + 4 * i + 2, x4[i].z);
        atomicAdd(dwrow + 4 * i + 3, x4[i].w);
    }
    out[OFF_IDX + gid] = (float)bi;

    // block loss reduction
#pragma unroll
    for (int o = 16; o > 0; o >>= 1)
        lsum += __shfl_xor_sync(~0u, lsum, o);
    if (lane == 0) s_red[warp] = lsum;
    __syncthreads();
    if (tid == 0) {
        float t = 0.f;
#pragma unroll
        for (int w = 0; w < SC_TPB / 32; w++) t += s_red[w];
        atomicAdd(&g_loss, t);
    }

    // flush block-local counts
    for (int i = tid; i < K_CB; i += SC_TPB) {
        float v = s_counts[i];
        if (v != 0.0f) atomicAdd(&g_counts[i], v);
    }
}

// ---------------------------------------------------------------------------
// Finalize stage 1: new_cluster_size, n-reduction, loss. One block.
// ---------------------------------------------------------------------------
__global__ void __launch_bounds__(K_CB)
vq_ncs_kernel(const float* __restrict__ ema_cs, float* __restrict__ out) {
    __shared__ float s_n[K_CB];
    const int k = threadIdx.x;

    float ncs = DECAY * ema_cs[k] + (1.0f - DECAY) * g_counts[k];
    out[OFF_CS + k] = ncs;

    s_n[k] = ncs;
    __syncthreads();
#pragma unroll
    for (int s = K_CB / 2; s > 0; s >>= 1) {
        if (k < s) s_n[k] += s_n[k + s];
        __syncthreads();
    }
    if (k == 0) {
        g_n = s_n[0];
        out[OFF_LOSS] = COMMIT * g_loss / (float)((size_t)N_TOK * D_EMB);
    }
}

// ---------------------------------------------------------------------------
// Finalize stage 2: element-parallel EMA weight + codebook update.
// ---------------------------------------------------------------------------
__global__ void __launch_bounds__(256)
vq_update_kernel(const float* __restrict__ ema_w, float* __restrict__ out) {
    const int idx = blockIdx.x * 256 + threadIdx.x;   // 0 .. K*D-1
    const int k = idx >> 6;

    float ncs = out[OFF_CS + k];
    float n = g_n;
    float smoothed = (ncs + EPSV) / (n + (float)K_CB * EPSV) * n;

    float w = DECAY * ema_w[idx] + (1.0f - DECAY) * g_dw[idx];
    out[OFF_EW + idx] = w;
    out[OFF_CB + idx] = w / smoothed;
}

// ---------------------------------------------------------------------------
extern "C" void kernel_launch(void* const* d_in, const int* in_sizes, int n_in,
                              void* d_out, int out_size) {
    const float* inputs   = (const float*)d_in[0];
    const float* codebook = (const float*)d_in[1];
    const float* ema_cs   = (const float*)d_in[2];
    const float* ema_w    = (const float*)d_in[3];
    float* out = (float*)d_out;

    vq_zero_kernel<<<(K_CB * D_EMB + 255) / 256, 256>>>();
    vq_prep_cb_kernel<<<1, K_CB>>>(codebook);
    vq_prep_x_kernel<<<N_TOK / 256, 256>>>(inputs);
    vq_screen_kernel<<<N_TOK / SC_TOKS, SC_TPB>>>(inputs, codebook, out);
    vq_ncs_kernel<<<1, K_CB>>>(ema_cs, out);
    vq_update_kernel<<<(K_CB * D_EMB) / 256, 256>>>(ema_w, out);
}